// round 5
// baseline (speedup 1.0000x reference)
#include <cuda_runtime.h>
#include <cuda_bf16.h>

// SurvEMD fused forward:
//   pred[j]   = (e==0 && j>=t) ? 10 : y_hat[j]
//   P(j)      = cumsum(softmax(pred))  (cumsum(exp)/total; logits<=10 so no max-sub needed)
//   target CDF T(j) closed-form from (t,e):
//     k  = (e==1) ? 1 : 64-t           (# of +10 logits)
//     q1 = 1/(k + (64-k)*exp(-20)), q0 = exp(-20)*q1
//     c1(j) = (e==1) ? (j>=t) : max(0, j-t+1)
//     T(j) = ((j+1)-c1)*q0 + c1*q1
//   loss_row = sum_j (P(j)-T(j))^2 ;  out = mean over rows.
//
// NOTE: t/e are int32 on disk (JAX x64 disabled downcasts the requested int64).
// Half-warp (16 lanes) per row, float4 per lane -> coalesced 256B row reads.
// Deterministic two-stage reduction (no atomics).

#define NBINS       64
#define BLOCK_T     256
#define GRID_B      2048
#define EXP_NEG20   2.0611536e-09f   // expf(-20.0f)

__device__ float g_partials[GRID_B];

__global__ __launch_bounds__(BLOCK_T)
void survemd_main(const float* __restrict__ y_hat,
                  const int* __restrict__ t_in,
                  const int* __restrict__ e_in,
                  int B)
{
    const int lane = threadIdx.x & 31;
    const int wid  = threadIdx.x >> 5;
    const int half = lane >> 4;          // which 16-lane group
    const int hl   = lane & 15;          // lane within group
    const unsigned hmask = 0xFFFFu << (half * 16);

    const int warpsPerBlock = BLOCK_T / 32;
    const int gwarp   = blockIdx.x * warpsPerBlock + wid;
    const int worker  = gwarp * 2 + half;                  // half-warp id
    const int nWorker = GRID_B * warpsPerBlock * 2;

    const int j0 = hl * 4;               // first bin this lane owns
    float acc = 0.0f;

    for (int row = worker; row < B; row += nWorker) {
        const int tr = t_in[row];
        const int er = e_in[row];
        const bool cen = (er == 0);

        const float4 y = ((const float4*)(y_hat + (size_t)row * NBINS))[hl];

        // pred logits
        float p0 = (cen && (j0 + 0) >= tr) ? 10.0f : y.x;
        float p1 = (cen && (j0 + 1) >= tr) ? 10.0f : y.y;
        float p2 = (cen && (j0 + 2) >= tr) ? 10.0f : y.z;
        float p3 = (cen && (j0 + 3) >= tr) ? 10.0f : y.w;

        float e0 = __expf(p0);
        float e1 = __expf(p1);
        float e2 = __expf(p2);
        float e3 = __expf(p3);

        // in-lane inclusive partial sums
        float s1 = e0;
        float s2 = s1 + e1;
        float s3 = s2 + e2;
        float s4 = s3 + e3;

        // inclusive scan of per-lane totals across the 16-lane group
        float sc = s4;
        #pragma unroll
        for (int off = 1; off < 16; off <<= 1) {
            float v = __shfl_up_sync(hmask, sc, off, 16);
            if (hl >= off) sc += v;
        }
        const float excl  = sc - s4;                       // exclusive prefix
        const float total = __shfl_sync(hmask, sc, 15, 16);
        const float inv   = 1.0f / total;

        // target CDF parameters
        const int   k     = cen ? (NBINS - tr) : 1;
        const float denom = (float)k + (float)(NBINS - k) * EXP_NEG20;
        const float q1    = 1.0f / denom;
        const float q0    = EXP_NEG20 * q1;

        // c1(j): count of +10 logits at indices <= j
        int c1_0, c1_1, c1_2, c1_3;
        if (cen) {
            c1_0 = max(0, j0 + 0 - tr + 1);
            c1_1 = max(0, j0 + 1 - tr + 1);
            c1_2 = max(0, j0 + 2 - tr + 1);
            c1_3 = max(0, j0 + 3 - tr + 1);
        } else {
            c1_0 = (j0 + 0) >= tr;
            c1_1 = (j0 + 1) >= tr;
            c1_2 = (j0 + 2) >= tr;
            c1_3 = (j0 + 3) >= tr;
        }

        float T0 = (float)(j0 + 1 - c1_0) * q0 + (float)c1_0 * q1;
        float T1 = (float)(j0 + 2 - c1_1) * q0 + (float)c1_1 * q1;
        float T2 = (float)(j0 + 3 - c1_2) * q0 + (float)c1_2 * q1;
        float T3 = (float)(j0 + 4 - c1_3) * q0 + (float)c1_3 * q1;

        float d0 = (excl + s1) * inv - T0;
        float d1 = (excl + s2) * inv - T1;
        float d2 = (excl + s3) * inv - T2;
        float d3 = (excl + s4) * inv - T3;

        acc += d0 * d0 + d1 * d1 + d2 * d2 + d3 * d3;
    }

    // warp reduction
    #pragma unroll
    for (int off = 16; off > 0; off >>= 1)
        acc += __shfl_xor_sync(0xFFFFFFFFu, acc, off);

    __shared__ float warpSums[BLOCK_T / 32];
    if (lane == 0) warpSums[wid] = acc;
    __syncthreads();

    if (wid == 0) {
        float s = (lane < warpsPerBlock) ? warpSums[lane] : 0.0f;
        #pragma unroll
        for (int off = 4; off > 0; off >>= 1)
            s += __shfl_xor_sync(0xFFFFFFFFu, s, off);
        if (lane == 0) g_partials[blockIdx.x] = s;
    }
}

__global__ __launch_bounds__(256)
void survemd_reduce(float* __restrict__ out, int B)
{
    __shared__ float sh[256];
    float s = 0.0f;
    for (int i = threadIdx.x; i < GRID_B; i += 256)
        s += g_partials[i];
    sh[threadIdx.x] = s;
    __syncthreads();
    #pragma unroll
    for (int stride = 128; stride >= 1; stride >>= 1) {
        if (threadIdx.x < stride) sh[threadIdx.x] += sh[threadIdx.x + stride];
        __syncthreads();
    }
    if (threadIdx.x == 0)
        out[0] = sh[0] / (float)B;
}

extern "C" void kernel_launch(void* const* d_in, const int* in_sizes, int n_in,
                              void* d_out, int out_size)
{
    const float* y_hat = (const float*)d_in[0];
    const int*   t     = (const int*)d_in[1];
    const int*   e     = (const int*)d_in[2];
    float*       out   = (float*)d_out;
    const int B = in_sizes[1];   // element count of t

    survemd_main<<<GRID_B, BLOCK_T>>>(y_hat, t, e, B);
    survemd_reduce<<<1, 256>>>(out, B);
}

// round 7
// speedup vs baseline: 1.6411x; 1.6411x over previous
#include <cuda_runtime.h>
#include <cuda_bf16.h>

// SurvEMD fused forward:
//   pred[j]   = (e==0 && j>=t) ? 10 : y_hat[j]
//   P(j)      = cumsum(softmax(pred))  (cumsum(exp)/total; logits<=10 so no max-sub needed)
//   target CDF T(j) closed-form from (t,e):
//     k  = (e==1) ? 1 : 64-t           (# of +10 logits)
//     q1 = 1/(k + (64-k)*exp(-20)), q0 = exp(-20)*q1
//     c1(j) = (e==1) ? (j>=t) : max(0, j-t+1)
//     T(j) = ((j+1)-c1)*q0 + c1*q1
//   loss_row = sum_j (P(j)-T(j))^2 ;  out = mean over rows.
//
// R5->R6: main loop unrolled x4 with front-batched loads (MLP 1 -> 4+) to fix
// the latency-bound profile (1.9 TB/s effective); final reduction fused into
// the main kernel via last-block ticket (deterministic, graph-safe).

#define NBINS       64
#define BLOCK_T     256
#define GRID_B      2048
#define EXP_NEG20   2.0611536e-09f   // expf(-20.0f)

__device__ float    g_partials[GRID_B];
__device__ unsigned g_count;         // zero-init; reset by last block each launch

__device__ __forceinline__ float row_loss(float4 y, int tr, int er,
                                          int j0, unsigned hmask, int hl)
{
    const bool cen = (er == 0);

    float p0 = (cen && (j0 + 0) >= tr) ? 10.0f : y.x;
    float p1 = (cen && (j0 + 1) >= tr) ? 10.0f : y.y;
    float p2 = (cen && (j0 + 2) >= tr) ? 10.0f : y.z;
    float p3 = (cen && (j0 + 3) >= tr) ? 10.0f : y.w;

    float e0 = __expf(p0);
    float e1 = __expf(p1);
    float e2 = __expf(p2);
    float e3 = __expf(p3);

    float s1 = e0;
    float s2 = s1 + e1;
    float s3 = s2 + e2;
    float s4 = s3 + e3;

    // inclusive scan of per-lane totals across the 16-lane group
    float sc = s4;
    #pragma unroll
    for (int off = 1; off < 16; off <<= 1) {
        float v = __shfl_up_sync(hmask, sc, off, 16);
        if (hl >= off) sc += v;
    }
    const float excl  = sc - s4;
    const float total = __shfl_sync(hmask, sc, 15, 16);
    const float inv   = 1.0f / total;

    const int   k     = cen ? (NBINS - tr) : 1;
    const float denom = (float)k + (float)(NBINS - k) * EXP_NEG20;
    const float q1    = 1.0f / denom;
    const float q0    = EXP_NEG20 * q1;

    int c1_0, c1_1, c1_2, c1_3;
    if (cen) {
        c1_0 = max(0, j0 + 0 - tr + 1);
        c1_1 = max(0, j0 + 1 - tr + 1);
        c1_2 = max(0, j0 + 2 - tr + 1);
        c1_3 = max(0, j0 + 3 - tr + 1);
    } else {
        c1_0 = (j0 + 0) >= tr;
        c1_1 = (j0 + 1) >= tr;
        c1_2 = (j0 + 2) >= tr;
        c1_3 = (j0 + 3) >= tr;
    }

    float T0 = (float)(j0 + 1 - c1_0) * q0 + (float)c1_0 * q1;
    float T1 = (float)(j0 + 2 - c1_1) * q0 + (float)c1_1 * q1;
    float T2 = (float)(j0 + 3 - c1_2) * q0 + (float)c1_2 * q1;
    float T3 = (float)(j0 + 4 - c1_3) * q0 + (float)c1_3 * q1;

    float d0 = (excl + s1) * inv - T0;
    float d1 = (excl + s2) * inv - T1;
    float d2 = (excl + s3) * inv - T2;
    float d3 = (excl + s4) * inv - T3;

    return d0 * d0 + d1 * d1 + d2 * d2 + d3 * d3;
}

__global__ __launch_bounds__(BLOCK_T)
void survemd_main(const float* __restrict__ y_hat,
                  const int* __restrict__ t_in,
                  const int* __restrict__ e_in,
                  float* __restrict__ out,
                  int B)
{
    const int lane = threadIdx.x & 31;
    const int wid  = threadIdx.x >> 5;
    const int half = lane >> 4;
    const int hl   = lane & 15;
    const unsigned hmask = 0xFFFFu << (half * 16);

    const int warpsPerBlock = BLOCK_T / 32;
    const int gwarp   = blockIdx.x * warpsPerBlock + wid;
    const int worker  = gwarp * 2 + half;
    const int stride  = GRID_B * warpsPerBlock * 2;   // 32768 workers

    const int j0 = hl * 4;
    float acc = 0.0f;

    int row = worker;

    // ---- main loop, unrolled x4 with front-batched loads (MLP >= 4) ----
    for (; row + 3 * stride < B; row += 4 * stride) {
        const int r0 = row, r1 = row + stride, r2 = row + 2 * stride, r3 = row + 3 * stride;

        // batch all global loads before any compute
        const int t0 = t_in[r0], t1 = t_in[r1], t2 = t_in[r2], t3 = t_in[r3];
        const int e0 = e_in[r0], e1 = e_in[r1], e2 = e_in[r2], e3 = e_in[r3];
        const float4 y0 = ((const float4*)(y_hat + (size_t)r0 * NBINS))[hl];
        const float4 y1 = ((const float4*)(y_hat + (size_t)r1 * NBINS))[hl];
        const float4 y2 = ((const float4*)(y_hat + (size_t)r2 * NBINS))[hl];
        const float4 y3 = ((const float4*)(y_hat + (size_t)r3 * NBINS))[hl];

        acc += row_loss(y0, t0, e0, j0, hmask, hl);
        acc += row_loss(y1, t1, e1, j0, hmask, hl);
        acc += row_loss(y2, t2, e2, j0, hmask, hl);
        acc += row_loss(y3, t3, e3, j0, hmask, hl);
    }
    // ---- tail ----
    for (; row < B; row += stride) {
        const int tr = t_in[row];
        const int er = e_in[row];
        const float4 y = ((const float4*)(y_hat + (size_t)row * NBINS))[hl];
        acc += row_loss(y, tr, er, j0, hmask, hl);
    }

    // block reduction
    #pragma unroll
    for (int off = 16; off > 0; off >>= 1)
        acc += __shfl_xor_sync(0xFFFFFFFFu, acc, off);

    __shared__ float warpSums[BLOCK_T / 32];
    if (lane == 0) warpSums[wid] = acc;
    __syncthreads();

    __shared__ bool isLast;
    if (threadIdx.x == 0) {
        float s = 0.0f;
        #pragma unroll
        for (int i = 0; i < BLOCK_T / 32; i++) s += warpSums[i];
        g_partials[blockIdx.x] = s;
        __threadfence();
        unsigned ticket = atomicAdd(&g_count, 1u);
        isLast = (ticket == (unsigned)(gridDim.x - 1));
    }
    __syncthreads();

    // last block reduces all partials (deterministic order) and resets counter
    if (isLast) {
        float s = 0.0f;
        for (int i = threadIdx.x; i < GRID_B; i += BLOCK_T)
            s += ((volatile float*)g_partials)[i];

        #pragma unroll
        for (int off = 16; off > 0; off >>= 1)
            s += __shfl_xor_sync(0xFFFFFFFFu, s, off);

        __shared__ float finalSums[BLOCK_T / 32];
        if (lane == 0) finalSums[wid] = s;
        __syncthreads();

        if (threadIdx.x == 0) {
            float tot = 0.0f;
            #pragma unroll
            for (int i = 0; i < BLOCK_T / 32; i++) tot += finalSums[i];
            out[0] = tot / (float)B;
            g_count = 0;   // reset for next graph replay
        }
    }
}

extern "C" void kernel_launch(void* const* d_in, const int* in_sizes, int n_in,
                              void* d_out, int out_size)
{
    const float* y_hat = (const float*)d_in[0];
    const int*   t     = (const int*)d_in[1];
    const int*   e     = (const int*)d_in[2];
    float*       out   = (float*)d_out;
    const int B = in_sizes[1];   // element count of t

    survemd_main<<<GRID_B, BLOCK_T>>>(y_hat, t, e, out, B);
}

// round 8
// speedup vs baseline: 1.9319x; 1.1772x over previous
#include <cuda_runtime.h>
#include <cuda_bf16.h>

// SurvEMD fused forward (see R7 header for math). R7->R8: issue-bound fix.
//   - rcp.approx instead of IEEE division (2x per row)
//   - c1 via single FFMA.SAT in float domain (exact: all values multiples of 1/64)
//   - single-predicate logit select (thr = cen ? tf : +INF)
//   - excl folded into inv-space; T folded into 2 FFMAs on precomputed jp1 regs

#define NBINS       64
#define BLOCK_T     256
#define GRID_B      2048
#define EXP_NEG20   2.0611536e-09f   // expf(-20.0f)

__device__ float    g_partials[GRID_B];
__device__ unsigned g_count;         // zero-init; reset by last block each launch

__device__ __forceinline__ float frcp(float x) {
    float r;
    asm("rcp.approx.f32 %0, %1;" : "=f"(r) : "f"(x));
    return r;
}

struct RowParams {
    float thr;       // select threshold on (j+1): jp1 > thr  <=>  (j>=t && censored)
    float iscale;    // c1 pre-scale  (cen ? 1/64 : 1)
    float nb;        // -tf * iscale
    float nq0;       // -q0
    float ndqe;      // -(q1-q0)*scalef
};

__device__ __forceinline__ RowParams make_params(int tr, int er)
{
    const bool  cen = (er == 0);
    const float tf  = (float)tr;

    const float kf    = cen ? (64.0f - tf) : 1.0f;
    const float denom = fmaf(64.0f - kf, EXP_NEG20, kf);
    const float q1    = frcp(denom);
    const float q0    = EXP_NEG20 * q1;
    const float dq    = q1 - q0;

    RowParams p;
    p.thr    = cen ? tf : 3.0e38f;
    p.iscale = cen ? 0.015625f : 1.0f;
    p.nb     = -tf * p.iscale;
    p.nq0    = -q0;
    p.ndqe   = -(dq * (cen ? 64.0f : 1.0f));
    return p;
}

// jp1[i] = j0 + 1 + i, precomputed per lane (loop-invariant registers).
__device__ __forceinline__ float row_loss(float4 y, RowParams p,
                                          float jp1a, float jp1b, float jp1c, float jp1d,
                                          unsigned hmask, int hl)
{
    // pred logits: replace with 10 where (j>=t && censored)
    float l0 = (jp1a > p.thr) ? 10.0f : y.x;
    float l1 = (jp1b > p.thr) ? 10.0f : y.y;
    float l2 = (jp1c > p.thr) ? 10.0f : y.z;
    float l3 = (jp1d > p.thr) ? 10.0f : y.w;

    float e0 = __expf(l0);
    float e1 = __expf(l1);
    float e2 = __expf(l2);
    float e3 = __expf(l3);

    // in-lane inclusive partial sums
    float s1 = e0;
    float s2 = s1 + e1;
    float s3 = s2 + e2;
    float s4 = s3 + e3;

    // inclusive scan of per-lane totals across the 16-lane group
    float sc = s4;
    #pragma unroll
    for (int off = 1; off < 16; off <<= 1) {
        float v = __shfl_up_sync(hmask, sc, off, 16);
        if (hl >= off) sc += v;
    }
    const float total   = __shfl_sync(hmask, sc, 15, 16);
    const float inv     = frcp(total);
    const float exclinv = (sc - s4) * inv;

    // c1 (scaled): saturate(fma(jp1, iscale, nb)); exact for multiples of 1/64
    float c0 = __saturatef(fmaf(jp1a, p.iscale, p.nb));
    float c1 = __saturatef(fmaf(jp1b, p.iscale, p.nb));
    float c2 = __saturatef(fmaf(jp1c, p.iscale, p.nb));
    float c3 = __saturatef(fmaf(jp1d, p.iscale, p.nb));

    // base = exclinv - (j+1)*q0 - c1*dqe
    float b0 = fmaf(c0, p.ndqe, fmaf(jp1a, p.nq0, exclinv));
    float b1 = fmaf(c1, p.ndqe, fmaf(jp1b, p.nq0, exclinv));
    float b2 = fmaf(c2, p.ndqe, fmaf(jp1c, p.nq0, exclinv));
    float b3 = fmaf(c3, p.ndqe, fmaf(jp1d, p.nq0, exclinv));

    // d = s*inv + base ; loss += d*d
    float d0 = fmaf(s1, inv, b0);
    float d1 = fmaf(s2, inv, b1);
    float d2 = fmaf(s3, inv, b2);
    float d3 = fmaf(s4, inv, b3);

    float r = d0 * d0;
    r = fmaf(d1, d1, r);
    r = fmaf(d2, d2, r);
    r = fmaf(d3, d3, r);
    return r;
}

__global__ __launch_bounds__(BLOCK_T)
void survemd_main(const float* __restrict__ y_hat,
                  const int* __restrict__ t_in,
                  const int* __restrict__ e_in,
                  float* __restrict__ out,
                  int B)
{
    const int lane = threadIdx.x & 31;
    const int wid  = threadIdx.x >> 5;
    const int half = lane >> 4;
    const int hl   = lane & 15;
    const unsigned hmask = 0xFFFFu << (half * 16);

    const int warpsPerBlock = BLOCK_T / 32;
    const int gwarp   = blockIdx.x * warpsPerBlock + wid;
    const int worker  = gwarp * 2 + half;
    const int stride  = GRID_B * warpsPerBlock * 2;   // 32768 workers

    const int   j0   = hl * 4;
    const float jp1a = (float)(j0 + 1);
    const float jp1b = (float)(j0 + 2);
    const float jp1c = (float)(j0 + 3);
    const float jp1d = (float)(j0 + 4);

    float acc = 0.0f;
    int row = worker;

    // main loop, unrolled x4 with front-batched loads (MLP >= 4)
    for (; row + 3 * stride < B; row += 4 * stride) {
        const int r0 = row, r1 = row + stride, r2 = row + 2 * stride, r3 = row + 3 * stride;

        const int t0 = t_in[r0], t1 = t_in[r1], t2 = t_in[r2], t3 = t_in[r3];
        const int e0 = e_in[r0], e1 = e_in[r1], e2 = e_in[r2], e3 = e_in[r3];
        const float4 y0 = ((const float4*)(y_hat + (size_t)r0 * NBINS))[hl];
        const float4 y1 = ((const float4*)(y_hat + (size_t)r1 * NBINS))[hl];
        const float4 y2 = ((const float4*)(y_hat + (size_t)r2 * NBINS))[hl];
        const float4 y3 = ((const float4*)(y_hat + (size_t)r3 * NBINS))[hl];

        acc += row_loss(y0, make_params(t0, e0), jp1a, jp1b, jp1c, jp1d, hmask, hl);
        acc += row_loss(y1, make_params(t1, e1), jp1a, jp1b, jp1c, jp1d, hmask, hl);
        acc += row_loss(y2, make_params(t2, e2), jp1a, jp1b, jp1c, jp1d, hmask, hl);
        acc += row_loss(y3, make_params(t3, e3), jp1a, jp1b, jp1c, jp1d, hmask, hl);
    }
    // tail
    for (; row < B; row += stride) {
        const int tr = t_in[row];
        const int er = e_in[row];
        const float4 y = ((const float4*)(y_hat + (size_t)row * NBINS))[hl];
        acc += row_loss(y, make_params(tr, er), jp1a, jp1b, jp1c, jp1d, hmask, hl);
    }

    // block reduction
    #pragma unroll
    for (int off = 16; off > 0; off >>= 1)
        acc += __shfl_xor_sync(0xFFFFFFFFu, acc, off);

    __shared__ float warpSums[BLOCK_T / 32];
    if (lane == 0) warpSums[wid] = acc;
    __syncthreads();

    __shared__ bool isLast;
    if (threadIdx.x == 0) {
        float s = 0.0f;
        #pragma unroll
        for (int i = 0; i < BLOCK_T / 32; i++) s += warpSums[i];
        g_partials[blockIdx.x] = s;
        __threadfence();
        unsigned ticket = atomicAdd(&g_count, 1u);
        isLast = (ticket == (unsigned)(gridDim.x - 1));
    }
    __syncthreads();

    // last block reduces all partials (deterministic order) and resets counter
    if (isLast) {
        float s = 0.0f;
        for (int i = threadIdx.x; i < GRID_B; i += BLOCK_T)
            s += ((volatile float*)g_partials)[i];

        #pragma unroll
        for (int off = 16; off > 0; off >>= 1)
            s += __shfl_xor_sync(0xFFFFFFFFu, s, off);

        __shared__ float finalSums[BLOCK_T / 32];
        if (lane == 0) finalSums[wid] = s;
        __syncthreads();

        if (threadIdx.x == 0) {
            float tot = 0.0f;
            #pragma unroll
            for (int i = 0; i < BLOCK_T / 32; i++) tot += finalSums[i];
            out[0] = tot / (float)B;
            g_count = 0;   // reset for next graph replay
        }
    }
}

extern "C" void kernel_launch(void* const* d_in, const int* in_sizes, int n_in,
                              void* d_out, int out_size)
{
    const float* y_hat = (const float*)d_in[0];
    const int*   t     = (const int*)d_in[1];
    const int*   e     = (const int*)d_in[2];
    float*       out   = (float*)d_out;
    const int B = in_sizes[1];   // element count of t

    survemd_main<<<GRID_B, BLOCK_T>>>(y_hat, t, e, out, B);
}

// round 9
// speedup vs baseline: 2.6387x; 1.3659x over previous
#include <cuda_runtime.h>
#include <cuda_bf16.h>

// SurvEMD fused forward (math: see prior rounds).
// R8->R9: 4 lanes per row (warp = 8 rows) to amortize scan/params/load overhead
// 4x; interleaved float4 assignment keeps LDG.128 at 8 lines/instr; jp1 table
// collapsed to 4 base constants + per-chunk hoisted FFMAs.

#define NBINS       64
#define BLOCK_T     256
#define GRID_B      2048
#define EXP_NEG20   2.0611536e-09f   // expf(-20.0f)
#define FULL        0xFFFFFFFFu

__device__ float    g_partials[GRID_B];
__device__ unsigned g_count;         // zero-init; reset by last block each launch

__device__ __forceinline__ float frcp(float x) {
    float r;
    asm("rcp.approx.f32 %0, %1;" : "=f"(r) : "f"(x));
    return r;
}

__global__ __launch_bounds__(BLOCK_T)
void survemd_main(const float* __restrict__ y_hat,
                  const int* __restrict__ t_in,
                  const int* __restrict__ e_in,
                  float* __restrict__ out,
                  int B)
{
    const int lane = threadIdx.x & 31;
    const int s    = lane & 3;    // sub-lane within row (owns f4 indices 4c+s)
    const int g    = lane >> 2;   // row within the warp's 8-row group
    const int wid  = threadIdx.x >> 5;

    const int warpsPerBlock = BLOCK_T / 32;
    const int gwarp   = blockIdx.x * warpsPerBlock + wid;
    const int wstride = GRID_B * warpsPerBlock * 8;     // rows per grid-stride step

    // per-lane element base: jp1(c,i) = (4s + i + 1) + 16c
    const float b0f = (float)(4 * s + 1);
    const float b1f = b0f + 1.0f;
    const float b2f = b0f + 2.0f;
    const float b3f = b0f + 3.0f;

    float acc = 0.0f;

    for (int base = gwarp * 8; base < B; base += wstride) {
        const int   row   = base + g;
        const int   rowc  = min(row, B - 1);
        const float vmask = (row < B) ? 1.0f : 0.0f;

        const int tr = t_in[rowc];
        const int er = e_in[rowc];

        // interleaved float4 loads: f4 index = rowc*16 + 4c + s
        const float4* yrow = (const float4*)y_hat + (size_t)rowc * 16 + s;
        float4 ya[4];
        ya[0] = yrow[0];
        ya[1] = yrow[4];
        ya[2] = yrow[8];
        ya[3] = yrow[12];

        // row params (computed per lane; 4 lanes redundant per row)
        const bool  cen = (er == 0);
        const float tf  = (float)tr;
        const float kf  = cen ? (64.0f - tf) : 1.0f;
        const float q1  = frcp(fmaf(64.0f - kf, EXP_NEG20, kf));
        const float q0  = EXP_NEG20 * q1;
        const float nq0 = -q0;
        const float dq  = q1 - q0;
        const float thr = cen ? tf : 3.0e38f;
        const float isc = cen ? 0.015625f : 1.0f;
        const float nb  = -tf * isc;
        const float ndqe = cen ? (dq * -64.0f) : -dq;

        // exps + in-lane inclusive partials per 4-element chunk
        float sl[4][4];
        #pragma unroll
        for (int c = 0; c < 4; c++) {
            const float thrc = thr - 16.0f * (float)c;
            float e0 = __expf((b0f > thrc) ? 10.0f : ya[c].x);
            float e1 = __expf((b1f > thrc) ? 10.0f : ya[c].y);
            float e2 = __expf((b2f > thrc) ? 10.0f : ya[c].z);
            float e3 = __expf((b3f > thrc) ? 10.0f : ya[c].w);
            sl[c][0] = e0;
            sl[c][1] = sl[c][0] + e1;
            sl[c][2] = sl[c][1] + e2;
            sl[c][3] = sl[c][2] + e3;
        }

        // exclusive quad prefixes: width-4 shfl scan per chunk + carry chain
        float E[4];
        float carry = 0.0f;
        #pragma unroll
        for (int c = 0; c < 4; c++) {
            float incl = sl[c][3];
            float v = __shfl_up_sync(FULL, incl, 1, 4);
            if (s >= 1) incl += v;
            v = __shfl_up_sync(FULL, incl, 2, 4);
            if (s >= 2) incl += v;
            const float W = __shfl_sync(FULL, incl, 3, 4);   // chunk total
            E[c] = carry + (incl - sl[c][3]);
            carry += W;
        }

        const float inv = frcp(carry);   // carry == row total

        float r = 0.0f;
        #pragma unroll
        for (int c = 0; c < 4; c++) {
            const float ecinv = E[c] * inv;
            const float hq = fmaf(16.0f * (float)c, nq0, ecinv);  // fold 16c into jp1*nq0
            const float hb = fmaf(16.0f * (float)c, isc, nb);     // fold 16c into c1 arg

            float c0 = __saturatef(fmaf(b0f, isc, hb));
            float c1 = __saturatef(fmaf(b1f, isc, hb));
            float c2 = __saturatef(fmaf(b2f, isc, hb));
            float c3 = __saturatef(fmaf(b3f, isc, hb));

            float bb0 = fmaf(c0, ndqe, fmaf(b0f, nq0, hq));
            float bb1 = fmaf(c1, ndqe, fmaf(b1f, nq0, hq));
            float bb2 = fmaf(c2, ndqe, fmaf(b2f, nq0, hq));
            float bb3 = fmaf(c3, ndqe, fmaf(b3f, nq0, hq));

            float d0 = fmaf(sl[c][0], inv, bb0);
            float d1 = fmaf(sl[c][1], inv, bb1);
            float d2 = fmaf(sl[c][2], inv, bb2);
            float d3 = fmaf(sl[c][3], inv, bb3);

            r = fmaf(d0, d0, r);
            r = fmaf(d1, d1, r);
            r = fmaf(d2, d2, r);
            r = fmaf(d3, d3, r);
        }

        acc = fmaf(vmask, r, acc);
    }

    // block reduction (warp sum covers all 8 rows' lane partials)
    #pragma unroll
    for (int off = 16; off > 0; off >>= 1)
        acc += __shfl_xor_sync(FULL, acc, off);

    __shared__ float warpSums[BLOCK_T / 32];
    if (lane == 0) warpSums[wid] = acc;
    __syncthreads();

    __shared__ bool isLast;
    if (threadIdx.x == 0) {
        float sm = 0.0f;
        #pragma unroll
        for (int i = 0; i < BLOCK_T / 32; i++) sm += warpSums[i];
        g_partials[blockIdx.x] = sm;
        __threadfence();
        unsigned ticket = atomicAdd(&g_count, 1u);
        isLast = (ticket == (unsigned)(gridDim.x - 1));
    }
    __syncthreads();

    // last block reduces all partials (deterministic order) and resets counter
    if (isLast) {
        float sm = 0.0f;
        for (int i = threadIdx.x; i < GRID_B; i += BLOCK_T)
            sm += ((volatile float*)g_partials)[i];

        #pragma unroll
        for (int off = 16; off > 0; off >>= 1)
            sm += __shfl_xor_sync(FULL, sm, off);

        __shared__ float finalSums[BLOCK_T / 32];
        if (lane == 0) finalSums[wid] = sm;
        __syncthreads();

        if (threadIdx.x == 0) {
            float tot = 0.0f;
            #pragma unroll
            for (int i = 0; i < BLOCK_T / 32; i++) tot += finalSums[i];
            out[0] = tot / (float)B;
            g_count = 0;   // reset for next graph replay
        }
    }
}

extern "C" void kernel_launch(void* const* d_in, const int* in_sizes, int n_in,
                              void* d_out, int out_size)
{
    const float* y_hat = (const float*)d_in[0];
    const int*   t     = (const int*)d_in[1];
    const int*   e     = (const int*)d_in[2];
    float*       out   = (float*)d_out;
    const int B = in_sizes[1];   // element count of t

    survemd_main<<<GRID_B, BLOCK_T>>>(y_hat, t, e, out, B);
}